// round 6
// baseline (speedup 1.0000x reference)
#include <cuda_runtime.h>
#include <cstdint>

#define Bsz 128
#define Lseq 1024
#define Hd 256
#define G3 768
#define CLS 8      // CTAs per cluster
#define WST 130    // u64 stride per weight row (128 pairs + 2 pad)
#define HST 130    // u64 stride per h row

typedef unsigned long long u64;

__device__ __forceinline__ u64 f2fma(u64 a, u64 b, u64 c) {
    u64 d; asm("fma.rn.f32x2 %0, %1, %2, %3;" : "=l"(d) : "l"(a), "l"(b), "l"(c)); return d;
}
__device__ __forceinline__ u64 dup2(float x) {
    u64 r; asm("mov.b64 %0, {%1, %1};" : "=l"(r) : "f"(x)); return r;
}
__device__ __forceinline__ void up2(u64 v, float& lo, float& hi) {
    asm("mov.b64 {%0, %1}, %2;" : "=f"(lo), "=f"(hi) : "l"(v));
}
__device__ __forceinline__ float hsum2(u64 v) {
    float lo, hi; up2(v, lo, hi); return lo + hi;
}
__device__ __forceinline__ uint32_t smem_u32(const void* p) {
    uint32_t a;
    asm("{ .reg .u64 t; cvta.to.shared.u64 t, %1; cvt.u32.u64 %0, t; }" : "=r"(a) : "l"(p));
    return a;
}
__device__ __forceinline__ uint32_t cta_rank() {
    uint32_t r; asm("mov.u32 %0, %%cluster_ctarank;" : "=r"(r)); return r;
}

// ---------------- scratch ----------------
__device__ float g_gi[(size_t)Lseq * G3 * Bsz];      // [t][3H][B]
__device__ float g_hseq0[(size_t)Lseq * Hd * Bsz];   // [t][k][b]
__device__ float g_hseq1[(size_t)Lseq * Hd * Bsz];

// ---------------- input-side GEMM: Gi[t][c][b] ----------------
__global__ __launch_bounds__(256) void gi_gemm_kernel(
    const float* __restrict__ xin, const float* __restrict__ W,
    const float* __restrict__ bias, int layer)
{
    __shared__ float Ws[16 * 132];
    __shared__ float As[16 * 132];

    const int t  = blockIdx.y;
    const int c0 = blockIdx.x * 128;
    const int tid = threadIdx.x;
    const int ty = tid >> 4;
    const int tx = tid & 15;

    u64 acc2[8][4];
#pragma unroll
    for (int i = 0; i < 8; i++)
#pragma unroll
        for (int j = 0; j < 4; j++) acc2[i][j] = 0ull;

    for (int k0 = 0; k0 < 256; k0 += 16) {
        {
            int row  = tid >> 2;
            int col4 = (tid & 3) * 4;
#pragma unroll
            for (int it = 0; it < 2; it++, row += 64) {
                float4 w = *(const float4*)(W + (size_t)(c0 + row) * 256 + k0 + col4);
                Ws[(col4 + 0) * 132 + row] = w.x;
                Ws[(col4 + 1) * 132 + row] = w.y;
                Ws[(col4 + 2) * 132 + row] = w.z;
                Ws[(col4 + 3) * 132 + row] = w.w;
            }
        }
        if (layer == 0) {
            int row  = tid >> 2;
            int col4 = (tid & 3) * 4;
#pragma unroll
            for (int it = 0; it < 2; it++, row += 64) {
                float4 a = *(const float4*)(xin + ((size_t)row * Lseq + t) * 256 + k0 + col4);
                As[(col4 + 0) * 132 + row] = a.x;
                As[(col4 + 1) * 132 + row] = a.y;
                As[(col4 + 2) * 132 + row] = a.z;
                As[(col4 + 3) * 132 + row] = a.w;
            }
        } else {
#pragma unroll
            for (int it = 0; it < 2; it++) {
                int idx = tid + it * 256;
                int k  = idx >> 5;
                int b4 = (idx & 31) * 4;
                float4 a = *(const float4*)(g_hseq0 + ((size_t)t * 256 + k0 + k) * 128 + b4);
                *(float4*)(As + k * 132 + b4) = a;
            }
        }
        __syncthreads();

#pragma unroll
        for (int kk = 0; kk < 16; kk++) {
            float wr[8];
            *(float4*)(wr)     = *(const float4*)(Ws + kk * 132 + ty * 4);
            *(float4*)(wr + 4) = *(const float4*)(Ws + kk * 132 + 64 + ty * 4);
            ulonglong2 aA = *(const ulonglong2*)(As + kk * 132 + tx * 4);
            ulonglong2 aB = *(const ulonglong2*)(As + kk * 132 + 64 + tx * 4);
#pragma unroll
            for (int i = 0; i < 8; i++) {
                u64 wd = dup2(wr[i]);
                acc2[i][0] = f2fma(aA.x, wd, acc2[i][0]);
                acc2[i][1] = f2fma(aA.y, wd, acc2[i][1]);
                acc2[i][2] = f2fma(aB.x, wd, acc2[i][2]);
                acc2[i][3] = f2fma(aB.y, wd, acc2[i][3]);
            }
        }
        __syncthreads();
    }

    float* gout = g_gi + (size_t)t * G3 * Bsz;
#pragma unroll
    for (int i = 0; i < 8; i++) {
        int c = (i < 4) ? (c0 + ty * 4 + i) : (c0 + 64 + ty * 4 + (i - 4));
        float bv = bias[c];
        float a0, a1, a2, a3, a4, a5, a6, a7;
        up2(acc2[i][0], a0, a1); up2(acc2[i][1], a2, a3);
        up2(acc2[i][2], a4, a5); up2(acc2[i][3], a6, a7);
        *(float4*)(gout + (size_t)c * Bsz + tx * 4) =
            make_float4(a0 + bv, a1 + bv, a2 + bv, a3 + bv);
        *(float4*)(gout + (size_t)c * Bsz + 64 + tx * 4) =
            make_float4(a4 + bv, a5 + bv, a6 + bv, a7 + bv);
    }
}

// ---------------- persistent GRU recurrence, cluster version ----------------
// grid 128, cluster 8. Cluster cl handles batches [cl*8, cl*8+8); CTA rank owns
// hidden units [rank*32, rank*32+32) (all 3 gates). h exchanged via DSMEM,
// synced with barrier.cluster once per step. No cross-cluster dependencies.
__global__ __launch_bounds__(512, 1) __cluster_dims__(CLS, 1, 1)
void gru_recur_kernel(
    const float* __restrict__ w_hh, const float* __restrict__ b_hh,
    const float* __restrict__ h0all, int layer)
{
    extern __shared__ __align__(16) char smraw[];
    u64*   w2_s  = (u64*)smraw;                 // 96 rows * WST = 12480 u64
    u64*   h_s   = w2_s + 96 * WST;             // 2 bufs * 8 b * HST = 2080 u64
    float* red_s = (float*)(h_s + 2 * 8 * HST); // 8 kq * 3 g * 32 j * 8 b = 6144 f
    float* bh_s  = red_s + 6144;                // 96 (+pad)

    const int tid  = threadIdx.x;
    const uint32_t rank = cta_rank();
    const int cl   = blockIdx.x >> 3;       // cluster index 0..15
    const int b0   = cl * 8;                // batch base
    const int j0   = (int)rank * 32;        // hidden base

    float* hseq = layer ? g_hseq1 : g_hseq0;

    // ---- stage weights as k-pairs: w2_s[g*32+j][kp] = {w[2kp], w[2kp+1]} ----
    for (int idx = tid; idx < 96 * 128; idx += 512) {
        int row = idx >> 7;                   // 0..95 : g*32 + j
        int kp  = idx & 127;
        int g = row >> 5, j = row & 31;
        const float2 w2 = *(const float2*)(w_hh + (size_t)(g * 256 + j0 + j) * 256 + 2 * kp);
        w2_s[row * WST + kp] = *(const u64*)&w2;
    }
    if (tid < 96) {
        int g = tid >> 5, j = tid & 31;
        bh_s[tid] = b_hh[g * 256 + j0 + j];
    }
    // ---- stage h0 into buffer 0: h_s[b][kp] pairs over k ----
    {
        const float* h0g = h0all + (size_t)layer * Bsz * Hd;  // [b][k]
        for (int idx = tid; idx < 8 * 128; idx += 512) {
            int bb = idx >> 7, kp = idx & 127;
            const float2 hv = *(const float2*)(h0g + (size_t)(b0 + bb) * 256 + 2 * kp);
            h_s[(0 * 8 + bb) * HST + kp] = *(const u64*)&hv;
        }
    }

    // dot-thread mapping: kq = tid>>6 (8), j = (tid>>1)&31, bg = tid&1 (4 b each)
    const int kq = tid >> 6;
    const int j  = (tid >> 1) & 31;
    const int bg = tid & 1;

    const ulonglong2* wr2 = (const ulonglong2*)(w2_s + (0 * 32 + j) * WST + kq * 16);
    const ulonglong2* wz2 = (const ulonglong2*)(w2_s + (1 * 32 + j) * WST + kq * 16);
    const ulonglong2* wn2 = (const ulonglong2*)(w2_s + (2 * 32 + j) * WST + kq * 16);

    // act-thread mapping (tid<128): jp = tid>>3 (16), b = tid&7
    const int jp = tid >> 3;
    const int ab = tid & 7;

    // gi prefetch for t=0 (2 j's x 3 gates, this batch)
    float gi_r[2], gi_z[2], gi_n[2];
    if (tid < 128) {
#pragma unroll
        for (int e = 0; e < 2; e++) {
            size_t gx = (size_t)(j0 + 2 * jp + e) * Bsz + b0 + ab;
            gi_r[e] = g_gi[gx];
            gi_z[e] = g_gi[32768 + gx];
            gi_n[e] = g_gi[65536 + gx];
        }
    }

    // one sync: all CTAs staged before any DSMEM writes arrive
    asm volatile("barrier.cluster.arrive.aligned;" ::: "memory");
    asm volatile("barrier.cluster.wait.aligned;" ::: "memory");

    for (int t = 0; t < Lseq; t++) {
        const int p = t & 1;

        // ---- dot: this thread's (j, 4 b, 32 k) ----
        u64 ar[4] = {0,0,0,0}, az[4] = {0,0,0,0}, an[4] = {0,0,0,0};
        const u64* hbase = h_s + (p * 8 + bg * 4) * HST + kq * 16;
#pragma unroll
        for (int c = 0; c < 8; c++) {
            ulonglong2 wr = wr2[c];
            ulonglong2 wz = wz2[c];
            ulonglong2 wn = wn2[c];
#pragma unroll
            for (int b = 0; b < 4; b++) {
                ulonglong2 h2 = *(const ulonglong2*)(hbase + b * HST + 2 * c);
                ar[b] = f2fma(h2.x, wr.x, ar[b]); ar[b] = f2fma(h2.y, wr.y, ar[b]);
                az[b] = f2fma(h2.x, wz.x, az[b]); az[b] = f2fma(h2.y, wz.y, az[b]);
                an[b] = f2fma(h2.x, wn.x, an[b]); an[b] = f2fma(h2.y, wn.y, an[b]);
            }
        }
        // ---- partials: red_s[kq][g][j][b8] ----
        {
            float* rb = red_s + ((kq * 3 + 0) * 32 + j) * 8 + bg * 4;
            *(float4*)rb = make_float4(hsum2(ar[0]), hsum2(ar[1]), hsum2(ar[2]), hsum2(ar[3]));
            rb = red_s + ((kq * 3 + 1) * 32 + j) * 8 + bg * 4;
            *(float4*)rb = make_float4(hsum2(az[0]), hsum2(az[1]), hsum2(az[2]), hsum2(az[3]));
            rb = red_s + ((kq * 3 + 2) * 32 + j) * 8 + bg * 4;
            *(float4*)rb = make_float4(hsum2(an[0]), hsum2(an[1]), hsum2(an[2]), hsum2(an[3]));
        }
        __syncthreads();

        // ---- reduce + activation + broadcast (128 act threads: 2 j x 1 b) ----
        if (tid < 128) {
            float hn[2];
#pragma unroll
            for (int e = 0; e < 2; e++) {
                int jj = 2 * jp + e;
                float sr = 0.f, sz = 0.f, sn = 0.f;
#pragma unroll
                for (int q = 0; q < 8; q++) {
                    sr += red_s[((q * 3 + 0) * 32 + jj) * 8 + ab];
                    sz += red_s[((q * 3 + 1) * 32 + jj) * 8 + ab];
                    sn += red_s[((q * 3 + 2) * 32 + jj) * 8 + ab];
                }
                sr += bh_s[jj];
                sz += bh_s[32 + jj];
                sn += bh_s[64 + jj];
                float r = 1.0f / (1.0f + __expf(-(gi_r[e] + sr)));
                float z = 1.0f / (1.0f + __expf(-(gi_z[e] + sz)));
                float n = tanhf(gi_n[e] + r * sn);
                // h_prev for this (jj, b): pair (j0+2jp, j0+2jp+1) -> element e
                float2 hp = *(const float2*)(h_s + (p * 8 + ab) * HST + (j0 >> 1) + jp);
                float hprev = e ? hp.y : hp.x;
                hn[e] = (1.0f - z) * n + z * hprev;
                // global h for later kernels
                hseq[(size_t)t * (Hd * Bsz) + (size_t)(j0 + jj) * Bsz + b0 + ab] = hn[e];
            }
            // DSMEM broadcast: write pair into every CTA's buffer p^1
            float2 hv = make_float2(hn[0], hn[1]);
            u64 hvu = *(const u64*)&hv;
            uint32_t laddr = smem_u32(h_s + ((p ^ 1) * 8 + ab) * HST + (j0 >> 1) + jp);
#pragma unroll
            for (int r = 0; r < CLS; r++) {
                uint32_t raddr;
                asm("mapa.shared::cluster.u32 %0, %1, %2;" : "=r"(raddr) : "r"(laddr), "r"(r));
                asm volatile("st.shared::cluster.u64 [%0], %1;" :: "r"(raddr), "l"(hvu) : "memory");
            }
        }

        // ---- cluster barrier; prefetch next gi between arrive and wait ----
        asm volatile("barrier.cluster.arrive.aligned;" ::: "memory");
        if (tid < 128 && t + 1 < Lseq) {
            const float* gi_n1 = g_gi + (size_t)(t + 1) * (G3 * Bsz);
#pragma unroll
            for (int e = 0; e < 2; e++) {
                size_t gx = (size_t)(j0 + 2 * jp + e) * Bsz + b0 + ab;
                gi_r[e] = gi_n1[gx];
                gi_z[e] = gi_n1[32768 + gx];
                gi_n[e] = gi_n1[65536 + gx];
            }
        }
        asm volatile("barrier.cluster.wait.aligned;" ::: "memory");
    }
}

// ---------------- transpose g_hseq1 [t][h][b] -> out [b][t][h] ----------------
__global__ __launch_bounds__(256) void transpose_out_kernel(float* __restrict__ out)
{
    __shared__ float tile[32 * 129];
    const int t  = blockIdx.y;
    const int h0 = blockIdx.x * 32;
    const int tid = threadIdx.x;
    const float* src = g_hseq1 + (size_t)t * (Hd * Bsz) + (size_t)h0 * Bsz;

    for (int idx = tid; idx < 4096; idx += 256) {
        int hh = idx >> 7, bb = idx & 127;
        tile[hh * 129 + bb] = src[idx];
    }
    __syncthreads();
    for (int idx = tid; idx < 4096; idx += 256) {
        int bb = idx >> 5, hh = idx & 31;
        out[(size_t)bb * Lseq * Hd + (size_t)t * Hd + h0 + hh] = tile[hh * 129 + bb];
    }
}

// ---------------- final hidden states ----------------
__global__ __launch_bounds__(256) void hn_kernel(float* __restrict__ out)
{
    int idx = blockIdx.x * blockDim.x + threadIdx.x;  // 0..65535
    int layer = idx >> 15;
    int b = (idx >> 8) & 127;
    int h = idx & 255;
    const float* hs = layer ? g_hseq1 : g_hseq0;
    out[(size_t)Bsz * Lseq * Hd + idx] =
        hs[(size_t)(Lseq - 1) * (Hd * Bsz) + (size_t)h * Bsz + b];
}

// ---------------- launcher ----------------
extern "C" void kernel_launch(void* const* d_in, const int* in_sizes, int n_in,
                              void* d_out, int out_size)
{
    const float* x     = (const float*)d_in[0];
    const float* h0    = (const float*)d_in[1];
    const float* w_ih0 = (const float*)d_in[2];
    const float* w_hh0 = (const float*)d_in[3];
    const float* b_ih0 = (const float*)d_in[4];
    const float* b_hh0 = (const float*)d_in[5];
    const float* w_ih1 = (const float*)d_in[6];
    const float* w_hh1 = (const float*)d_in[7];
    const float* b_ih1 = (const float*)d_in[8];
    const float* b_hh1 = (const float*)d_in[9];
    float* out = (float*)d_out;

    const size_t smem = (96 * WST + 2 * 8 * HST) * sizeof(u64)
                      + (6144 + 128) * sizeof(float);   // ~141.5 KB
    cudaFuncSetAttribute(gru_recur_kernel,
                         cudaFuncAttributeMaxDynamicSharedMemorySize, (int)smem);

    gi_gemm_kernel<<<dim3(6, Lseq), 256>>>(x, w_ih0, b_ih0, 0);
    gru_recur_kernel<<<128, 512, smem>>>(w_hh0, b_hh0, h0, 0);
    gi_gemm_kernel<<<dim3(6, Lseq), 256>>>(x, w_ih1, b_ih1, 1);
    gru_recur_kernel<<<128, 512, smem>>>(w_hh1, b_hh1, h0, 1);
    transpose_out_kernel<<<dim3(8, Lseq), 256>>>(out);
    if (out_size >= (int)((size_t)Bsz * Lseq * Hd + 2 * Bsz * Hd))
        hn_kernel<<<256, 256>>>(out);
}